// round 4
// baseline (speedup 1.0000x reference)
#include <cuda_runtime.h>
#include <math.h>

#define NN 100000
#define EE 3200000

// ---------------- scratch (device globals; no runtime allocation) ----------------
__device__ float g_deg[NN];
__device__ float g_dis[NN];
__device__ int   g_cnt[NN];
__device__ int   g_off[NN];
__device__ int   g_cur[NN];
__device__ unsigned long long g_edge[EE];   // packed {norm:f32 (hi), src:i32 (lo)}
__device__ __align__(16) float g_fa[NN*48]; // conv1 features, ping
__device__ __align__(16) float g_fb[NN*48]; // conv1 features, pong
__device__ __align__(16) float g_oa[NN*4];  // conv2 state ping (3 used + pad)
__device__ __align__(16) float g_ob[NN*4];  // conv2 state pong
__device__ __align__(16) float g_root2[NN*4];
__device__ int   g_bsum[128];

// ---------------- gcn_norm + CSR build ----------------
__global__ void k_zero() {
    int i = blockIdx.x*blockDim.x + threadIdx.x;
    if (i < NN) { g_deg[i] = 0.f; g_cnt[i] = 0; }
}

__global__ void k_deg(const int* __restrict__ col, const float* __restrict__ ew) {
    int e = blockIdx.x*blockDim.x + threadIdx.x;
    if (e < EE) {
        int c = col[e];
        atomicAdd(&g_deg[c], ew[e]);
        atomicAdd(&g_cnt[c], 1);
    }
}

// block scan over counts; also computes dis (fused elementwise)
__global__ void k_scanA() {
    __shared__ int s[1024];
    int i = blockIdx.x*1024 + threadIdx.x;
    if (i < NN) {
        float d = g_deg[i];
        g_dis[i] = d > 0.f ? rsqrtf(fmaxf(d, 1e-12f)) : 0.f;
    }
    int v = (i < NN) ? g_cnt[i] : 0;
    s[threadIdx.x] = v;
    __syncthreads();
    for (int off = 1; off < 1024; off <<= 1) {
        int t = (threadIdx.x >= off) ? s[threadIdx.x - off] : 0;
        __syncthreads();
        s[threadIdx.x] += t;
        __syncthreads();
    }
    if (i < NN) g_off[i] = s[threadIdx.x] - v;   // exclusive within block
    if (threadIdx.x == 1023) g_bsum[blockIdx.x] = s[1023];
}

// parallel exclusive scan over block sums (nb <= 128)
__global__ void k_scanB(int nb) {
    __shared__ int s[128];
    int t = threadIdx.x;
    int v = (t < nb) ? g_bsum[t] : 0;
    s[t] = v;
    __syncthreads();
    for (int off = 1; off < 128; off <<= 1) {
        int u = (t >= off) ? s[t - off] : 0;
        __syncthreads();
        s[t] += u;
        __syncthreads();
    }
    if (t < nb) g_bsum[t] = s[t] - v;  // exclusive
}

__global__ void k_scanC() {
    int i = blockIdx.x*blockDim.x + threadIdx.x;
    if (i < NN) {
        int o = g_off[i] + g_bsum[i >> 10];
        g_off[i] = o;
        g_cur[i] = o;
    }
}

__global__ void k_scatter(const int* __restrict__ row, const int* __restrict__ colv,
                          const float* __restrict__ ew) {
    int e = blockIdx.x*blockDim.x + threadIdx.x;
    if (e < EE) {
        int r = row[e], c = colv[e];
        float nm = g_dis[r] * ew[e] * g_dis[c];
        int p = atomicAdd(&g_cur[c], 1);
        unsigned long long pk =
            (((unsigned long long)(unsigned int)__float_as_int(nm)) << 32) | (unsigned int)r;
        g_edge[p] = pk;
    }
}

// ---------------- conv1 ----------------
// Warp per node: lanes stride over edges (coalesced edge loads), shuffle-reduce,
// then lanes 0..11 write the initial feature state (fused old k_feat0).
// feat layout per node: 12 float4 chunks; chunk ch = cidx*3 + k holds
// features [4*cidx .. 4*cidx+3] of stack k.
__global__ void __launch_bounds__(256)
k_ax(const float* __restrict__ x, const float* __restrict__ iw,
     const float* __restrict__ rw, const float* __restrict__ bs) {
    int n = (blockIdx.x*256 + threadIdx.x) >> 5;   // grid exact: 12500*8 = 100000
    int lane = threadIdx.x & 31;
    int st = g_off[n], cn = g_cnt[n];
    float s = 0.f;
    for (int j = st + lane; j < st + cn; j += 32) {
        unsigned long long pk = g_edge[j];
        s += __int_as_float((int)(pk >> 32)) * __ldg(&x[(int)(pk & 0xffffffffu)]);
    }
    #pragma unroll
    for (int off = 16; off; off >>= 1) s += __shfl_xor_sync(0xffffffffu, s, off);
    // all lanes now hold Ax[n]
    float xv = __ldg(&x[n]);
    if (lane < 12) {
        int k = lane % 3, cidx = lane / 3;
        float4 o; float* po = (float*)&o;
        #pragma unroll
        for (int i = 0; i < 4; i++) {
            int f = cidx*4 + i;
            po[i] = fmaxf(s*__ldg(&iw[k*16+f]) + xv*__ldg(&rw[k*16+f]) + __ldg(&bs[k*16+f]), 0.f);
        }
        ((float4*)g_fa)[n*12 + lane] = o;
    }
}

// Warp per node, dual-edge: half h processes edges st+h, st+h+2, ... ;
// lane c<12 owns float4 chunk c. Per edge the 12 lanes load 192 contiguous
// bytes -> ~2 L1 wavefronts/edge (vs 12 in the thread-gather version).
// Epilogue: combine halves (shfl), exchange via smem, fused 16x16 matmul
// + root + relu. finalMode fuses mean/BN/relu + conv2 input/root transforms.
__global__ void __launch_bounds__(256)
k_iter1(int srcIsB, int finalMode,
        const float* __restrict__ x, const float* __restrict__ w,
        const float* __restrict__ rw, const float* __restrict__ bs,
        const float* __restrict__ bng, const float* __restrict__ bnb,
        const float* __restrict__ bnm, const float* __restrict__ bnv,
        const float* __restrict__ iw2, const float* __restrict__ rw2,
        const float* __restrict__ b2) {
    __shared__ float wsh[768];
    __shared__ float rwsh[48], bsh[48];
    __shared__ float ex[8][56];
    for (int i = threadIdx.x; i < 768; i += 256) wsh[i] = w[i];
    if (threadIdx.x < 48) { rwsh[threadIdx.x] = rw[threadIdx.x]; bsh[threadIdx.x] = bs[threadIdx.x]; }
    __syncthreads();

    int warp = threadIdx.x >> 5;
    int lane = threadIdx.x & 31;
    int h = lane >> 4, c = lane & 15;
    bool act = c < 12;
    int n = blockIdx.x*8 + warp;                 // grid exact: 12500*8 = 100000
    int st = g_off[n], cn = g_cnt[n];
    int e_end = st + cn;
    const float4* F = (const float4*)(srcIsB ? g_fb : g_fa);
    float*        D = srcIsB ? g_fa : g_fb;

    float4 acc = make_float4(0.f, 0.f, 0.f, 0.f);
    int j = st + h;
    while (j + 2 < e_end) {
        unsigned long long p0 = g_edge[j];
        unsigned long long p1 = g_edge[j+2];
        float m0 = __int_as_float((int)(p0 >> 32));
        float m1 = __int_as_float((int)(p1 >> 32));
        int s0 = (int)(p0 & 0xffffffffu);
        int s1 = (int)(p1 & 0xffffffffu);
        if (act) {
            float4 v0 = __ldg(&F[s0*12 + c]);
            float4 v1 = __ldg(&F[s1*12 + c]);
            acc.x += m0*v0.x + m1*v1.x;
            acc.y += m0*v0.y + m1*v1.y;
            acc.z += m0*v0.z + m1*v1.z;
            acc.w += m0*v0.w + m1*v1.w;
        }
        j += 4;
    }
    if (j < e_end) {
        unsigned long long p0 = g_edge[j];
        float m0 = __int_as_float((int)(p0 >> 32));
        int s0 = (int)(p0 & 0xffffffffu);
        if (act) {
            float4 v0 = __ldg(&F[s0*12 + c]);
            acc.x += m0*v0.x; acc.y += m0*v0.y; acc.z += m0*v0.z; acc.w += m0*v0.w;
        }
    }

    // combine the two halves (lane c and lane 16+c hold partials of chunk c)
    acc.x += __shfl_xor_sync(0xffffffffu, acc.x, 16);
    acc.y += __shfl_xor_sync(0xffffffffu, acc.y, 16);
    acc.z += __shfl_xor_sync(0xffffffffu, acc.z, 16);
    acc.w += __shfl_xor_sync(0xffffffffu, acc.w, 16);

    int kk = c % 3, cidx = c / 3;   // chunk c = cidx*3 + kk
    bool act0 = (h == 0) && act;
    // exchange: af[k*16 + f] for the matmul
    if (act0) {
        float* e = ex[warp] + kk*16 + cidx*4;
        e[0] = acc.x; e[1] = acc.y; e[2] = acc.z; e[3] = acc.w;
    }
    __syncwarp();

    // y = af * W[k] + x*root_w + bias, relu  (A(out)w == A(out w))
    float4 yv = make_float4(0.f, 0.f, 0.f, 0.f);
    if (act0) {
        const float* af = ex[warp] + kk*16;
        const float* wk = wsh + kk*256;
        float xv = __ldg(&x[n]);
        float* py = (float*)&yv;
        #pragma unroll
        for (int i = 0; i < 4; i++) {
            int oo = cidx*4 + i;
            float y = 0.f;
            #pragma unroll
            for (int f = 0; f < 16; f++) y += af[f] * wk[f*16 + oo];
            py[i] = fmaxf(y + xv*rwsh[kk*16+oo] + bsh[kk*16+oo], 0.f);
        }
    }
    __syncwarp();

    if (!finalMode) {
        if (act0) ((float4*)D)[n*12 + c] = yv;
        return;
    }

    // ---- final iteration: fuse mean over stacks + BN + relu + conv2 prep ----
    if (act0) {
        float* e = ex[warp] + kk*16 + cidx*4;
        e[0] = yv.x; e[1] = yv.y; e[2] = yv.z; e[3] = yv.w;
    }
    __syncwarp();
    if (lane < 16) {
        float m = (ex[warp][lane] + ex[warp][16+lane] + ex[warp][32+lane]) * (1.f/3.f);
        float sc = __ldg(&bng[lane]) * rsqrtf(__ldg(&bnv[lane]) + 1e-5f);
        ex[warp][lane] = fmaxf((m - __ldg(&bnm[lane]))*sc + __ldg(&bnb[lane]), 0.f);
    }
    __syncwarp();
    if (lane == 0) {
        float hv[16];
        #pragma unroll
        for (int f = 0; f < 16; f++) hv[f] = ex[warp][f];
        float o[3] = {0,0,0}, r[3] = {0,0,0};
        #pragma unroll
        for (int k2 = 0; k2 < 3; k2++) {
            #pragma unroll
            for (int f = 0; f < 16; f++) {
                o[k2] += hv[f] * __ldg(&iw2[k2*16+f]);
                r[k2] += hv[f] * __ldg(&rw2[k2*16+f]);
            }
            r[k2] += __ldg(&b2[k2]);
        }
        float4 ov; ov.x=o[0]; ov.y=o[1]; ov.z=o[2]; ov.w=0.f;
        float4 rv; rv.x=r[0]; rv.y=r[1]; rv.z=r[2]; rv.w=0.f;
        ((float4*)g_oa)[n] = ov;
        ((float4*)g_root2)[n] = rv;
    }
}

// ---------------- conv2 ----------------
// Warp per node: lanes stride over edges (coalesced edge loads), one float4
// gather per edge, shuffle-reduce 3 accumulators; last call fuses sigmoid.
__global__ void __launch_bounds__(256)
k_iter2(int srcIsB, const float* __restrict__ w2, int applyW,
        float* __restrict__ finalOut) {
    int n = (blockIdx.x*256 + threadIdx.x) >> 5;   // grid exact
    int lane = threadIdx.x & 31;
    int st = g_off[n], cn = g_cnt[n];
    const float4* S = (const float4*)(srcIsB ? g_ob : g_oa);
    float a0 = 0.f, a1 = 0.f, a2 = 0.f;
    for (int j = st + lane; j < st + cn; j += 32) {
        unsigned long long pk = g_edge[j];
        float m = __int_as_float((int)(pk >> 32));
        float4 v = __ldg(&S[(int)(pk & 0xffffffffu)]);
        a0 += m*v.x; a1 += m*v.y; a2 += m*v.z;
    }
    #pragma unroll
    for (int off = 16; off; off >>= 1) {
        a0 += __shfl_xor_sync(0xffffffffu, a0, off);
        a1 += __shfl_xor_sync(0xffffffffu, a1, off);
        a2 += __shfl_xor_sync(0xffffffffu, a2, off);
    }
    if (lane == 0) {
        if (applyW) {
            a0 *= __ldg(&w2[0]); a1 *= __ldg(&w2[1]); a2 *= __ldg(&w2[2]);
        }
        float4 rt = ((const float4*)g_root2)[n];
        a0 += rt.x; a1 += rt.y; a2 += rt.z;
        if (finalOut) {
            float s = (a0 + a1 + a2) * (1.f/3.f);
            finalOut[n] = 1.f / (1.f + expf(-s));
        } else {
            float4* Dp = (float4*)(srcIsB ? g_oa : g_ob);
            float4 o; o.x = a0; o.y = a1; o.z = a2; o.w = 0.f;
            Dp[n] = o;
        }
    }
}

// ---------------- driver ----------------
extern "C" void kernel_launch(void* const* d_in, const int* in_sizes, int n_in,
                              void* d_out, int out_size) {
    const float* x    = (const float*)d_in[0];
    const int*   ei   = (const int*)  d_in[1];
    const float* ew   = (const float*)d_in[2];
    const float* c1iw = (const float*)d_in[3];
    const float* c1w  = (const float*)d_in[4];
    const float* c1rw = (const float*)d_in[5];
    const float* c1b  = (const float*)d_in[6];
    const float* bng  = (const float*)d_in[7];
    const float* bnb  = (const float*)d_in[8];
    const float* bnm  = (const float*)d_in[9];
    const float* bnv  = (const float*)d_in[10];
    const float* c2iw = (const float*)d_in[11];
    const float* c2w  = (const float*)d_in[12];
    const float* c2rw = (const float*)d_in[13];
    const float* c2b  = (const float*)d_in[14];
    float* out = (float*)d_out;

    const int* row = ei;
    const int* col = ei + EE;

    const int NG = (NN + 255) / 256;
    const int EG = (EE + 255) / 256;
    const int NB = (NN + 1023) / 1024;
    const int WG = 12500;   // warp-per-node grids: 12500 blocks x 8 warps = 100000

    // gcn_norm + CSR build
    k_zero<<<NG, 256>>>();
    k_deg<<<EG, 256>>>(col, ew);
    k_scanA<<<NB, 1024>>>();
    k_scanB<<<1, 128>>>(NB);
    k_scanC<<<NG, 256>>>();
    k_scatter<<<EG, 256>>>(row, col, ew);

    // conv1: rank-1 first propagation (+fused feature init), then 3 SpMM iters
    k_ax<<<WG, 256>>>(x, c1iw, c1rw, c1b);
    k_iter1<<<WG, 256>>>(0, 0, x, c1w, c1rw, c1b, bng, bnb, bnm, bnv, c2iw, c2rw, c2b); // fa->fb
    k_iter1<<<WG, 256>>>(1, 0, x, c1w, c1rw, c1b, bng, bnb, bnm, bnv, c2iw, c2rw, c2b); // fb->fa
    k_iter1<<<WG, 256>>>(0, 1, x, c1w, c1rw, c1b, bng, bnb, bnm, bnv, c2iw, c2rw, c2b); // fa-> (fused BN+prep2)

    // conv2 (Fout=1), last iteration fuses sigmoid -> out
    k_iter2<<<WG, 256>>>(0, c2w, 0, nullptr);  // oa -> ob
    k_iter2<<<WG, 256>>>(1, c2w, 1, nullptr);  // ob -> oa
    k_iter2<<<WG, 256>>>(0, c2w, 1, nullptr);  // oa -> ob
    k_iter2<<<WG, 256>>>(1, c2w, 1, out);      // ob -> sigmoid -> out
}

// round 5
// speedup vs baseline: 1.0318x; 1.0318x over previous
#include <cuda_runtime.h>
#include <math.h>

#define NN 100000
#define EE 3200000
#define NBLK 98   // ceil(NN/1024)

// ---------------- scratch (device globals; no runtime allocation) ----------------
// zeroed each run by one cudaMemsetAsync (memset node in the graph)
struct ZBlock {
    float        deg[NN];
    int          cnt[NN];
    unsigned int agg[NBLK];   // decoupled-lookback aggregates (bit31 = ready)
};
__device__ ZBlock gz;

__device__ float g_dis[NN];
__device__ int   g_off[NN];
__device__ int   g_cur[NN];
__device__ unsigned long long g_edge[EE];   // packed {norm:f32 (hi), src:i32 (lo)}
__device__ __align__(16) float g_fa[NN*48]; // conv1 features, ping
__device__ __align__(16) float g_fb[NN*48]; // conv1 features, pong
__device__ float g_ca[NN];                  // conv2 Horner scalar, ping
__device__ float g_cb[NN];                  // conv2 Horner scalar, pong
__device__ __align__(16) float4 g_s[NN];    // (s3, s2, s1, s0) per node

// ---------------- gcn_norm + CSR build ----------------
__global__ void k_deg(const int* __restrict__ col, const float* __restrict__ ew) {
    int e = blockIdx.x*blockDim.x + threadIdx.x;
    if (e < EE) {
        int c = col[e];
        atomicAdd(&gz.deg[c], ew[e]);
        atomicAdd(&gz.cnt[c], 1);
    }
}

// fused: dis + block scan + decoupled lookback + offsets (replaces scanA/B/C)
__global__ void __launch_bounds__(1024) k_scan() {
    __shared__ int s[1024];
    __shared__ int sprefix;
    int tid = threadIdx.x, bid = blockIdx.x;
    int i = bid*1024 + tid;
    if (i < NN) {
        float d = gz.deg[i];
        g_dis[i] = d > 0.f ? rsqrtf(fmaxf(d, 1e-12f)) : 0.f;
    }
    int v = (i < NN) ? gz.cnt[i] : 0;
    s[tid] = v;
    __syncthreads();
    for (int off = 1; off < 1024; off <<= 1) {
        int t = (tid >= off) ? s[tid - off] : 0;
        __syncthreads();
        s[tid] += t;
        __syncthreads();
    }
    int incl = s[tid];
    if (tid == 0) {
        unsigned int aggregate = (unsigned int)s[1023];
        atomicExch(&gz.agg[bid], aggregate | 0x80000000u);
    }
    // lookback: sum aggregates of all previous blocks (all blocks co-resident)
    if (tid < 32) {
        unsigned int sum = 0;
        for (int b = tid; b < bid; b += 32) {
            unsigned int a;
            do { a = *(volatile unsigned int*)&gz.agg[b]; } while (!(a & 0x80000000u));
            sum += a & 0x7fffffffu;
        }
        #pragma unroll
        for (int off = 16; off; off >>= 1) sum += __shfl_xor_sync(0xffffffffu, sum, off);
        if (tid == 0) sprefix = (int)sum;
    }
    __syncthreads();
    if (i < NN) {
        int o = sprefix + incl - v;   // exclusive global offset
        g_off[i] = o;
        g_cur[i] = o;
    }
}

__global__ void k_scatter(const int* __restrict__ row, const int* __restrict__ colv,
                          const float* __restrict__ ew) {
    int e = blockIdx.x*blockDim.x + threadIdx.x;
    if (e < EE) {
        int r = row[e], c = colv[e];
        float nm = g_dis[r] * ew[e] * g_dis[c];
        int p = atomicAdd(&g_cur[c], 1);
        unsigned long long pk =
            (((unsigned long long)(unsigned int)__float_as_int(nm)) << 32) | (unsigned int)r;
        g_edge[p] = pk;
    }
}

// ---------------- conv1 ----------------
// Warp per node: lanes stride over edges, shuffle-reduce Ax, then lanes 0..11
// write the initial feature state.
// feat layout per node: 12 float4 chunks; chunk ch = cidx*3 + k holds
// features [4*cidx .. 4*cidx+3] of stack k.
__global__ void __launch_bounds__(256)
k_ax(const float* __restrict__ x, const float* __restrict__ iw,
     const float* __restrict__ rw, const float* __restrict__ bs) {
    int n = (blockIdx.x*256 + threadIdx.x) >> 5;   // grid exact: 12500*8 = 100000
    int lane = threadIdx.x & 31;
    int st = g_off[n], cn = gz.cnt[n];
    float s = 0.f;
    for (int j = st + lane; j < st + cn; j += 32) {
        unsigned long long pk = g_edge[j];
        s += __int_as_float((int)(pk >> 32)) * __ldg(&x[(int)(pk & 0xffffffffu)]);
    }
    #pragma unroll
    for (int off = 16; off; off >>= 1) s += __shfl_xor_sync(0xffffffffu, s, off);
    float xv = __ldg(&x[n]);
    if (lane < 12) {
        int k = lane % 3, cidx = lane / 3;
        float4 o; float* po = (float*)&o;
        #pragma unroll
        for (int i = 0; i < 4; i++) {
            int f = cidx*4 + i;
            po[i] = fmaxf(s*__ldg(&iw[k*16+f]) + xv*__ldg(&rw[k*16+f]) + __ldg(&bs[k*16+f]), 0.f);
        }
        ((float4*)g_fa)[n*12 + lane] = o;
    }
}

// Warp per node, dual-edge halves, UNROLL-4 pipelined gather:
// half h processes edges st+h, st+h+2, ...; per main iteration 4 edge words
// are hoisted, then 4 independent 12-lane gathers issue -> 8 latency chains
// per warp in flight. Epilogue: shfl-combine halves, smem exchange, fused
// 16x16 W matmul + root + relu. finalMode fuses mean/BN/relu + the conv2
// Horner prep (scalar z and s3..s0).
__global__ void __launch_bounds__(256)
k_iter1(int srcIsB, int finalMode,
        const float* __restrict__ x, const float* __restrict__ w,
        const float* __restrict__ rw, const float* __restrict__ bs,
        const float* __restrict__ bng, const float* __restrict__ bnb,
        const float* __restrict__ bnm, const float* __restrict__ bnv,
        const float* __restrict__ iw2, const float* __restrict__ w2,
        const float* __restrict__ rw2, const float* __restrict__ b2) {
    __shared__ float wsh[768];
    __shared__ float rwsh[48], bsh[48];
    __shared__ float ex[8][56];
    for (int i = threadIdx.x; i < 768; i += 256) wsh[i] = w[i];
    if (threadIdx.x < 48) { rwsh[threadIdx.x] = rw[threadIdx.x]; bsh[threadIdx.x] = bs[threadIdx.x]; }
    __syncthreads();

    int warp = threadIdx.x >> 5;
    int lane = threadIdx.x & 31;
    int h = lane >> 4, c = lane & 15;
    bool act = c < 12;
    int n = blockIdx.x*8 + warp;                 // grid exact
    int st = g_off[n], cn = gz.cnt[n];
    int e_end = st + cn;
    const float4* F = (const float4*)(srcIsB ? g_fb : g_fa);
    float*        D = srcIsB ? g_fa : g_fb;

    float4 acc = make_float4(0.f, 0.f, 0.f, 0.f);
    int j = st + h;
    // main loop: 4 edges per half per iteration, loads hoisted
    while (j + 6 < e_end) {
        unsigned long long p0 = g_edge[j];
        unsigned long long p1 = g_edge[j+2];
        unsigned long long p2 = g_edge[j+4];
        unsigned long long p3 = g_edge[j+6];
        float m0 = __int_as_float((int)(p0 >> 32));
        float m1 = __int_as_float((int)(p1 >> 32));
        float m2 = __int_as_float((int)(p2 >> 32));
        float m3 = __int_as_float((int)(p3 >> 32));
        int s0 = (int)(p0 & 0xffffffffu);
        int s1 = (int)(p1 & 0xffffffffu);
        int s2 = (int)(p2 & 0xffffffffu);
        int s3 = (int)(p3 & 0xffffffffu);
        if (act) {
            float4 v0 = __ldg(&F[s0*12 + c]);
            float4 v1 = __ldg(&F[s1*12 + c]);
            float4 v2 = __ldg(&F[s2*12 + c]);
            float4 v3 = __ldg(&F[s3*12 + c]);
            acc.x += m0*v0.x + m1*v1.x + m2*v2.x + m3*v3.x;
            acc.y += m0*v0.y + m1*v1.y + m2*v2.y + m3*v3.y;
            acc.z += m0*v0.z + m1*v1.z + m2*v2.z + m3*v3.z;
            acc.w += m0*v0.w + m1*v1.w + m2*v2.w + m3*v3.w;
        }
        j += 8;
    }
    while (j < e_end) {
        unsigned long long p0 = g_edge[j];
        float m0 = __int_as_float((int)(p0 >> 32));
        int s0 = (int)(p0 & 0xffffffffu);
        if (act) {
            float4 v0 = __ldg(&F[s0*12 + c]);
            acc.x += m0*v0.x; acc.y += m0*v0.y; acc.z += m0*v0.z; acc.w += m0*v0.w;
        }
        j += 2;
    }

    // combine the two halves
    acc.x += __shfl_xor_sync(0xffffffffu, acc.x, 16);
    acc.y += __shfl_xor_sync(0xffffffffu, acc.y, 16);
    acc.z += __shfl_xor_sync(0xffffffffu, acc.z, 16);
    acc.w += __shfl_xor_sync(0xffffffffu, acc.w, 16);

    int kk = c % 3, cidx = c / 3;   // chunk c = cidx*3 + kk
    bool act0 = (h == 0) && act;
    if (act0) {
        float* e = ex[warp] + kk*16 + cidx*4;
        e[0] = acc.x; e[1] = acc.y; e[2] = acc.z; e[3] = acc.w;
    }
    __syncwarp();

    // y = af * W[k] + x*root_w + bias, relu  (A(out)w == A(out w))
    float4 yv = make_float4(0.f, 0.f, 0.f, 0.f);
    if (act0) {
        const float* af = ex[warp] + kk*16;
        const float* wk = wsh + kk*256;
        float xv = __ldg(&x[n]);
        float* py = (float*)&yv;
        #pragma unroll
        for (int i = 0; i < 4; i++) {
            int oo = cidx*4 + i;
            float y = 0.f;
            #pragma unroll
            for (int f = 0; f < 16; f++) y += af[f] * wk[f*16 + oo];
            py[i] = fmaxf(y + xv*rwsh[kk*16+oo] + bsh[kk*16+oo], 0.f);
        }
    }
    __syncwarp();

    if (!finalMode) {
        if (act0) ((float4*)D)[n*12 + c] = yv;
        return;
    }

    // ---- final iteration: mean over stacks + BN + relu + conv2 Horner prep ----
    if (act0) {
        float* e = ex[warp] + kk*16 + cidx*4;
        e[0] = yv.x; e[1] = yv.y; e[2] = yv.z; e[3] = yv.w;
    }
    __syncwarp();
    if (lane < 16) {
        float m = (ex[warp][lane] + ex[warp][16+lane] + ex[warp][32+lane]) * (1.f/3.f);
        float sc = __ldg(&bng[lane]) * rsqrtf(__ldg(&bnv[lane]) + 1e-5f);
        ex[warp][lane] = fmaxf((m - __ldg(&bnm[lane]))*sc + __ldg(&bnb[lane]), 0.f);
    }
    __syncwarp();
    if (lane == 0) {
        float hv[16];
        #pragma unroll
        for (int f = 0; f < 16; f++) hv[f] = ex[warp][f];
        // o_k = h . iw2_k ; r_k = h . rw2_k + b_k
        float o[3] = {0,0,0}, r[3] = {0,0,0};
        #pragma unroll
        for (int k2 = 0; k2 < 3; k2++) {
            #pragma unroll
            for (int f = 0; f < 16; f++) {
                o[k2] += hv[f] * __ldg(&iw2[k2*16+f]);
                r[k2] += hv[f] * __ldg(&rw2[k2*16+f]);
            }
            r[k2] += __ldg(&b2[k2]);
        }
        // Horner constants: z = sum w_k^3 o_k ; s_i = sum w_k^i r_k
        float z = 0.f, s3v = 0.f, s2v = 0.f, s1v = 0.f, s0v = 0.f;
        #pragma unroll
        for (int k2 = 0; k2 < 3; k2++) {
            float wv = __ldg(&w2[k2]);
            float w2p = wv*wv, w3p = w2p*wv;
            z   += w3p * o[k2];
            s3v += w3p * r[k2];
            s2v += w2p * r[k2];
            s1v += wv  * r[k2];
            s0v += r[k2];
        }
        g_ca[n] = z;
        float4 sv; sv.x = s3v; sv.y = s2v; sv.z = s1v; sv.w = s0v;
        g_s[n] = sv;
    }
}

// ---------------- conv2: 4 scalar Horner SpMV passes ----------------
// result = sigmoid( (A(A(A(A z + s3) + s2) + s1) + s0) / 3 )
__global__ void __launch_bounds__(256)
k_sp(int pass, float* __restrict__ finalOut) {
    int n = (blockIdx.x*256 + threadIdx.x) >> 5;   // grid exact
    int lane = threadIdx.x & 31;
    int st = g_off[n], cn = gz.cnt[n];
    const float* src = (pass & 1) ? g_cb : g_ca;
    float s = 0.f;
    for (int j = st + lane; j < st + cn; j += 32) {
        unsigned long long pk = g_edge[j];
        s += __int_as_float((int)(pk >> 32)) * __ldg(&src[(int)(pk & 0xffffffffu)]);
    }
    #pragma unroll
    for (int off = 16; off; off >>= 1) s += __shfl_xor_sync(0xffffffffu, s, off);
    if (lane == 0) {
        float4 sv = __ldg(&g_s[n]);
        float si = (pass == 0) ? sv.x : (pass == 1) ? sv.y : (pass == 2) ? sv.z : sv.w;
        float cval = s + si;
        if (pass == 3) {
            finalOut[n] = 1.f / (1.f + expf(-cval * (1.f/3.f)));
        } else {
            float* dst = (pass & 1) ? g_ca : g_cb;
            dst[n] = cval;
        }
    }
}

// ---------------- driver ----------------
extern "C" void kernel_launch(void* const* d_in, const int* in_sizes, int n_in,
                              void* d_out, int out_size) {
    const float* x    = (const float*)d_in[0];
    const int*   ei   = (const int*)  d_in[1];
    const float* ew   = (const float*)d_in[2];
    const float* c1iw = (const float*)d_in[3];
    const float* c1w  = (const float*)d_in[4];
    const float* c1rw = (const float*)d_in[5];
    const float* c1b  = (const float*)d_in[6];
    const float* bng  = (const float*)d_in[7];
    const float* bnb  = (const float*)d_in[8];
    const float* bnm  = (const float*)d_in[9];
    const float* bnv  = (const float*)d_in[10];
    const float* c2iw = (const float*)d_in[11];
    const float* c2w  = (const float*)d_in[12];
    const float* c2rw = (const float*)d_in[13];
    const float* c2b  = (const float*)d_in[14];
    float* out = (float*)d_out;

    const int* row = ei;
    const int* col = ei + EE;

    const int EG = (EE + 255) / 256;
    const int WG = 12500;   // warp-per-node grids: 12500 blocks x 8 warps = 100000

    // zero deg/cnt/agg in one memset node
    void* zp = nullptr;
    cudaGetSymbolAddress(&zp, gz);
    cudaMemsetAsync(zp, 0, sizeof(ZBlock), 0);

    // gcn_norm + CSR build
    k_deg<<<EG, 256>>>(col, ew);
    k_scan<<<NBLK, 1024>>>();
    k_scatter<<<EG, 256>>>(row, col, ew);

    // conv1: rank-1 first propagation (+fused feature init), then 3 SpMM iters
    k_ax<<<WG, 256>>>(x, c1iw, c1rw, c1b);
    k_iter1<<<WG, 256>>>(0, 0, x, c1w, c1rw, c1b, bng, bnb, bnm, bnv, c2iw, c2w, c2rw, c2b); // fa->fb
    k_iter1<<<WG, 256>>>(1, 0, x, c1w, c1rw, c1b, bng, bnb, bnm, bnv, c2iw, c2w, c2rw, c2b); // fb->fa
    k_iter1<<<WG, 256>>>(0, 1, x, c1w, c1rw, c1b, bng, bnb, bnm, bnv, c2iw, c2w, c2rw, c2b); // fa-> Horner prep

    // conv2: 4 scalar Horner passes, last fuses sigmoid -> out
    k_sp<<<WG, 256>>>(0, nullptr);  // ca -> cb  (+s3)
    k_sp<<<WG, 256>>>(1, nullptr);  // cb -> ca  (+s2)
    k_sp<<<WG, 256>>>(2, nullptr);  // ca -> cb  (+s1)
    k_sp<<<WG, 256>>>(3, out);      // cb -> sigmoid((c+s0)/3) -> out
}

// round 7
// speedup vs baseline: 1.1845x; 1.1481x over previous
#include <cuda_runtime.h>
#include <cuda_fp16.h>
#include <math.h>

#define NN 100000
#define EE 3200000
#define NBLK 98   // ceil(NN/1024)

// ---------------- scratch (device globals; no runtime allocation) ----------------
// zeroed each run by one cudaMemsetAsync (memset node in the graph)
struct ZBlock {
    unsigned long long pk[NN];  // {count:24bits | fixed-point weight sum:40bits}
    unsigned int agg[NBLK];     // decoupled-lookback aggregates (bit31 = ready)
};
__device__ ZBlock gz;

__device__ float g_dis[NN];
__device__ int   g_cnt[NN];
__device__ int   g_off[NN];
__device__ int   g_cur[NN];
__device__ unsigned long long g_edge[EE];     // packed {norm:f32 (hi), src:i32 (lo)}
__device__ __align__(16) uint2 g_fa[NN*16];   // conv1 fp16 feats ping (12 of 16 chunks used; 128B/node)
__device__ __align__(16) uint2 g_fb[NN*16];   // conv1 fp16 feats pong
__device__ float g_ca[NN];                    // conv2 Horner scalar, ping
__device__ float g_cb[NN];                    // conv2 Horner scalar, pong
__device__ __align__(16) float4 g_s[NN];      // (s3, s2, s1, s0) per node

// ---------------- gcn_norm + CSR build ----------------
// ONE packed 64-bit atomic per edge: high 24 bits count, low 40 bits
// fixed-point (2^-28) sum of edge weights. More exact than float atomics.
__global__ void k_deg(const int* __restrict__ col, const float* __restrict__ ew) {
    int e = blockIdx.x*blockDim.x + threadIdx.x;
    if (e < EE) {
        unsigned long long inc = (1ull << 40) |
            (unsigned long long)(ew[e] * 268435456.f + 0.5f);
        atomicAdd(&gz.pk[col[e]], inc);
    }
}

// fused: unpack deg/cnt + dis + block scan + decoupled lookback + offsets
__global__ void __launch_bounds__(1024) k_scan() {
    __shared__ int s[1024];
    __shared__ int sprefix;
    int tid = threadIdx.x, bid = blockIdx.x;
    int i = bid*1024 + tid;
    int v = 0;
    if (i < NN) {
        unsigned long long p = gz.pk[i];
        v = (int)(p >> 40);
        float d = (float)(p & 0xFFFFFFFFFFull) * 3.7252902984619141e-09f; // 2^-28
        g_dis[i] = d > 0.f ? rsqrtf(fmaxf(d, 1e-12f)) : 0.f;
        g_cnt[i] = v;
    }
    s[tid] = v;
    __syncthreads();
    for (int off = 1; off < 1024; off <<= 1) {
        int t = (tid >= off) ? s[tid - off] : 0;
        __syncthreads();
        s[tid] += t;
        __syncthreads();
    }
    int incl = s[tid];
    if (tid == 0) {
        unsigned int aggregate = (unsigned int)s[1023];
        atomicExch(&gz.agg[bid], aggregate | 0x80000000u);
    }
    if (tid < 32) {
        unsigned int sum = 0;
        for (int b = tid; b < bid; b += 32) {
            unsigned int a;
            do { a = *(volatile unsigned int*)&gz.agg[b]; } while (!(a & 0x80000000u));
            sum += a & 0x7fffffffu;
        }
        #pragma unroll
        for (int off = 16; off; off >>= 1) sum += __shfl_xor_sync(0xffffffffu, sum, off);
        if (tid == 0) sprefix = (int)sum;
    }
    __syncthreads();
    if (i < NN) {
        int o = sprefix + incl - v;   // exclusive global offset
        g_off[i] = o;
        g_cur[i] = o;
    }
}

__global__ void k_scatter(const int* __restrict__ row, const int* __restrict__ colv,
                          const float* __restrict__ ew) {
    int e = blockIdx.x*blockDim.x + threadIdx.x;
    if (e < EE) {
        int r = row[e], c = colv[e];
        float nm = g_dis[r] * ew[e] * g_dis[c];
        int p = atomicAdd(&g_cur[c], 1);
        unsigned long long pk =
            (((unsigned long long)(unsigned int)__float_as_int(nm)) << 32) | (unsigned int)r;
        g_edge[p] = pk;
    }
}

// ---------------- conv1 ----------------
// feat layout per node: 16 uint2 chunks (12 used, 128B record, 128B-aligned);
// chunk ch = cidx*3 + k holds fp16 features [4*cidx .. 4*cidx+3] of stack k.
__device__ __forceinline__ uint2 pack4h(float a, float b, float c, float d) {
    __half2 lo = __floats2half2_rn(a, b);
    __half2 hi = __floats2half2_rn(c, d);
    uint2 o;
    o.x = *(unsigned int*)&lo;
    o.y = *(unsigned int*)&hi;
    return o;
}

// Warp per node: lanes stride over edges, shuffle-reduce Ax, then lanes 0..11
// write the initial fp16 feature state.
__global__ void __launch_bounds__(256)
k_ax(const float* __restrict__ x, const float* __restrict__ iw,
     const float* __restrict__ rw, const float* __restrict__ bs) {
    int n = (blockIdx.x*256 + threadIdx.x) >> 5;   // grid exact: 12500*8 = 100000
    int lane = threadIdx.x & 31;
    int st = g_off[n], cn = g_cnt[n];
    float s = 0.f;
    for (int j = st + lane; j < st + cn; j += 32) {
        unsigned long long pk = g_edge[j];
        s += __int_as_float((int)(pk >> 32)) * __ldg(&x[(int)(pk & 0xffffffffu)]);
    }
    #pragma unroll
    for (int off = 16; off; off >>= 1) s += __shfl_xor_sync(0xffffffffu, s, off);
    float xv = __ldg(&x[n]);
    if (lane < 12) {
        int k = lane % 3, cidx = lane / 3;
        float f0, f1, f2, f3;
        {
            int f = cidx*4;
            f0 = fmaxf(s*__ldg(&iw[k*16+f+0]) + xv*__ldg(&rw[k*16+f+0]) + __ldg(&bs[k*16+f+0]), 0.f);
            f1 = fmaxf(s*__ldg(&iw[k*16+f+1]) + xv*__ldg(&rw[k*16+f+1]) + __ldg(&bs[k*16+f+1]), 0.f);
            f2 = fmaxf(s*__ldg(&iw[k*16+f+2]) + xv*__ldg(&rw[k*16+f+2]) + __ldg(&bs[k*16+f+2]), 0.f);
            f3 = fmaxf(s*__ldg(&iw[k*16+f+3]) + xv*__ldg(&rw[k*16+f+3]) + __ldg(&bs[k*16+f+3]), 0.f);
        }
        g_fa[n*16 + lane] = pack4h(f0, f1, f2, f3);
    }
}

// Warp per node, dual-edge halves, unroll-4 pipelined fp16 gather.
// Per edge the 12 lanes load 96 contiguous bytes inside a 128B-aligned record.
// fp32 accumulate; epilogue: shfl-combine halves, smem exchange, fused
// 16x16 W matmul + root + relu. finalMode fuses mean/BN/relu + conv2 Horner prep.
__global__ void __launch_bounds__(256)
k_iter1(int srcIsB, int finalMode,
        const float* __restrict__ x, const float* __restrict__ w,
        const float* __restrict__ rw, const float* __restrict__ bs,
        const float* __restrict__ bng, const float* __restrict__ bnb,
        const float* __restrict__ bnm, const float* __restrict__ bnv,
        const float* __restrict__ iw2, const float* __restrict__ w2,
        const float* __restrict__ rw2, const float* __restrict__ b2) {
    __shared__ float wsh[768];
    __shared__ float rwsh[48], bsh[48];
    __shared__ float ex[8][56];
    for (int i = threadIdx.x; i < 768; i += 256) wsh[i] = w[i];
    if (threadIdx.x < 48) { rwsh[threadIdx.x] = rw[threadIdx.x]; bsh[threadIdx.x] = bs[threadIdx.x]; }
    __syncthreads();

    int warp = threadIdx.x >> 5;
    int lane = threadIdx.x & 31;
    int h = lane >> 4, c = lane & 15;
    bool act = c < 12;
    int n = blockIdx.x*8 + warp;                 // grid exact
    int st = g_off[n], cn = g_cnt[n];
    int e_end = st + cn;
    const uint2* F = srcIsB ? g_fb : g_fa;
    uint2*       D = srcIsB ? g_fa : g_fb;

    float4 acc = make_float4(0.f, 0.f, 0.f, 0.f);
    int j = st + h;
    while (j + 6 < e_end) {
        unsigned long long p0 = g_edge[j];
        unsigned long long p1 = g_edge[j+2];
        unsigned long long p2 = g_edge[j+4];
        unsigned long long p3 = g_edge[j+6];
        float m0 = __int_as_float((int)(p0 >> 32));
        float m1 = __int_as_float((int)(p1 >> 32));
        float m2 = __int_as_float((int)(p2 >> 32));
        float m3 = __int_as_float((int)(p3 >> 32));
        int s0 = (int)(p0 & 0xffffffffu);
        int s1 = (int)(p1 & 0xffffffffu);
        int s2 = (int)(p2 & 0xffffffffu);
        int s3 = (int)(p3 & 0xffffffffu);
        if (act) {
            uint2 q0 = __ldg(&F[s0*16 + c]);
            uint2 q1 = __ldg(&F[s1*16 + c]);
            uint2 q2 = __ldg(&F[s2*16 + c]);
            uint2 q3 = __ldg(&F[s3*16 + c]);
            float2 a0 = __half22float2(*(const __half2*)&q0.x);
            float2 b0 = __half22float2(*(const __half2*)&q0.y);
            float2 a1 = __half22float2(*(const __half2*)&q1.x);
            float2 b1 = __half22float2(*(const __half2*)&q1.y);
            float2 a2 = __half22float2(*(const __half2*)&q2.x);
            float2 b2v = __half22float2(*(const __half2*)&q2.y);
            float2 a3 = __half22float2(*(const __half2*)&q3.x);
            float2 b3 = __half22float2(*(const __half2*)&q3.y);
            acc.x += m0*a0.x + m1*a1.x + m2*a2.x + m3*a3.x;
            acc.y += m0*a0.y + m1*a1.y + m2*a2.y + m3*a3.y;
            acc.z += m0*b0.x + m1*b1.x + m2*b2v.x + m3*b3.x;
            acc.w += m0*b0.y + m1*b1.y + m2*b2v.y + m3*b3.y;
        }
        j += 8;
    }
    while (j < e_end) {
        unsigned long long p0 = g_edge[j];
        float m0 = __int_as_float((int)(p0 >> 32));
        int s0 = (int)(p0 & 0xffffffffu);
        if (act) {
            uint2 q0 = __ldg(&F[s0*16 + c]);
            float2 a0 = __half22float2(*(const __half2*)&q0.x);
            float2 b0 = __half22float2(*(const __half2*)&q0.y);
            acc.x += m0*a0.x; acc.y += m0*a0.y; acc.z += m0*b0.x; acc.w += m0*b0.y;
        }
        j += 2;
    }

    // combine the two halves
    acc.x += __shfl_xor_sync(0xffffffffu, acc.x, 16);
    acc.y += __shfl_xor_sync(0xffffffffu, acc.y, 16);
    acc.z += __shfl_xor_sync(0xffffffffu, acc.z, 16);
    acc.w += __shfl_xor_sync(0xffffffffu, acc.w, 16);

    int kk = c % 3, cidx = c / 3;   // chunk c = cidx*3 + kk
    bool act0 = (h == 0) && act;
    if (act0) {
        float* e = ex[warp] + kk*16 + cidx*4;
        e[0] = acc.x; e[1] = acc.y; e[2] = acc.z; e[3] = acc.w;
    }
    __syncwarp();

    // y = af * W[k] + x*root_w + bias, relu  (A(out)w == A(out w))
    float4 yv = make_float4(0.f, 0.f, 0.f, 0.f);
    if (act0) {
        const float* af = ex[warp] + kk*16;
        const float* wk = wsh + kk*256;
        float xv = __ldg(&x[n]);
        float* py = (float*)&yv;
        #pragma unroll
        for (int i = 0; i < 4; i++) {
            int oo = cidx*4 + i;
            float y = 0.f;
            #pragma unroll
            for (int f = 0; f < 16; f++) y += af[f] * wk[f*16 + oo];
            py[i] = fmaxf(y + xv*rwsh[kk*16+oo] + bsh[kk*16+oo], 0.f);
        }
    }
    __syncwarp();

    if (!finalMode) {
        if (act0) D[n*16 + c] = pack4h(yv.x, yv.y, yv.z, yv.w);
        return;
    }

    // ---- final iteration: mean over stacks + BN + relu + conv2 Horner prep ----
    if (act0) {
        float* e = ex[warp] + kk*16 + cidx*4;
        e[0] = yv.x; e[1] = yv.y; e[2] = yv.z; e[3] = yv.w;
    }
    __syncwarp();
    if (lane < 16) {
        float m = (ex[warp][lane] + ex[warp][16+lane] + ex[warp][32+lane]) * (1.f/3.f);
        float sc = __ldg(&bng[lane]) * rsqrtf(__ldg(&bnv[lane]) + 1e-5f);
        ex[warp][lane] = fmaxf((m - __ldg(&bnm[lane]))*sc + __ldg(&bnb[lane]), 0.f);
    }
    __syncwarp();
    if (lane == 0) {
        float hv[16];
        #pragma unroll
        for (int f = 0; f < 16; f++) hv[f] = ex[warp][f];
        float o[3] = {0,0,0}, r[3] = {0,0,0};
        #pragma unroll
        for (int k2 = 0; k2 < 3; k2++) {
            #pragma unroll
            for (int f = 0; f < 16; f++) {
                o[k2] += hv[f] * __ldg(&iw2[k2*16+f]);
                r[k2] += hv[f] * __ldg(&rw2[k2*16+f]);
            }
            r[k2] += __ldg(&b2[k2]);
        }
        float z = 0.f, s3v = 0.f, s2v = 0.f, s1v = 0.f, s0v = 0.f;
        #pragma unroll
        for (int k2 = 0; k2 < 3; k2++) {
            float wv = __ldg(&w2[k2]);
            float w2p = wv*wv, w3p = w2p*wv;
            z   += w3p * o[k2];
            s3v += w3p * r[k2];
            s2v += w2p * r[k2];
            s1v += wv  * r[k2];
            s0v += r[k2];
        }
        g_ca[n] = z;
        float4 sv; sv.x = s3v; sv.y = s2v; sv.z = s1v; sv.w = s0v;
        g_s[n] = sv;
    }
}

// ---------------- conv2: 4 scalar Horner SpMV passes ----------------
// result = sigmoid( (A(A(A(A z + s3) + s2) + s1) + s0) / 3 )
// Half-warp per node: 2 nodes/warp, 4-level shuffle reduce.
__global__ void __launch_bounds__(256)
k_sp(int pass, float* __restrict__ finalOut) {
    int n = (blockIdx.x*256 + threadIdx.x) >> 4;   // grid exact: 6250*16 = 100000
    int lane = threadIdx.x & 15;
    int st = g_off[n], cn = g_cnt[n];
    const float* src = (pass & 1) ? g_cb : g_ca;
    float s = 0.f;
    for (int j = st + lane; j < st + cn; j += 16) {
        unsigned long long pk = g_edge[j];
        s += __int_as_float((int)(pk >> 32)) * __ldg(&src[(int)(pk & 0xffffffffu)]);
    }
    #pragma unroll
    for (int off = 8; off; off >>= 1) s += __shfl_xor_sync(0xffffffffu, s, off);
    if (lane == 0) {
        float4 sv = __ldg(&g_s[n]);
        float si = (pass == 0) ? sv.x : (pass == 1) ? sv.y : (pass == 2) ? sv.z : sv.w;
        float cval = s + si;
        if (pass == 3) {
            finalOut[n] = 1.f / (1.f + expf(-cval * (1.f/3.f)));
        } else {
            float* dst = (pass & 1) ? g_ca : g_cb;
            dst[n] = cval;
        }
    }
}

// ---------------- driver ----------------
extern "C" void kernel_launch(void* const* d_in, const int* in_sizes, int n_in,
                              void* d_out, int out_size) {
    const float* x    = (const float*)d_in[0];
    const int*   ei   = (const int*)  d_in[1];
    const float* ew   = (const float*)d_in[2];
    const float* c1iw = (const float*)d_in[3];
    const float* c1w  = (const float*)d_in[4];
    const float* c1rw = (const float*)d_in[5];
    const float* c1b  = (const float*)d_in[6];
    const float* bng  = (const float*)d_in[7];
    const float* bnb  = (const float*)d_in[8];
    const float* bnm  = (const float*)d_in[9];
    const float* bnv  = (const float*)d_in[10];
    const float* c2iw = (const float*)d_in[11];
    const float* c2w  = (const float*)d_in[12];
    const float* c2rw = (const float*)d_in[13];
    const float* c2b  = (const float*)d_in[14];
    float* out = (float*)d_out;

    const int* row = ei;
    const int* col = ei + EE;

    const int EG = (EE + 255) / 256;
    const int WG = 12500;   // warp-per-node: 12500 blocks x 8 warps = 100000
    const int HG = 6250;    // half-warp-per-node: 6250 blocks x 16 halves = 100000

    // zero packed deg/cnt + lookback aggregates in one memset node
    void* zp = nullptr;
    cudaGetSymbolAddress(&zp, gz);
    cudaMemsetAsync(zp, 0, sizeof(ZBlock), 0);

    // gcn_norm + CSR build
    k_deg<<<EG, 256>>>(col, ew);
    k_scan<<<NBLK, 1024>>>();
    k_scatter<<<EG, 256>>>(row, col, ew);

    // conv1: rank-1 first propagation (+fused feature init), then 3 SpMM iters
    k_ax<<<WG, 256>>>(x, c1iw, c1rw, c1b);
    k_iter1<<<WG, 256>>>(0, 0, x, c1w, c1rw, c1b, bng, bnb, bnm, bnv, c2iw, c2w, c2rw, c2b); // fa->fb
    k_iter1<<<WG, 256>>>(1, 0, x, c1w, c1rw, c1b, bng, bnb, bnm, bnv, c2iw, c2w, c2rw, c2b); // fb->fa
    k_iter1<<<WG, 256>>>(0, 1, x, c1w, c1rw, c1b, bng, bnb, bnm, bnv, c2iw, c2w, c2rw, c2b); // fa-> Horner prep

    // conv2: 4 scalar Horner passes, last fuses sigmoid -> out
    k_sp<<<HG, 256>>>(0, nullptr);  // ca -> cb  (+s3)
    k_sp<<<HG, 256>>>(1, nullptr);  // cb -> ca  (+s2)
    k_sp<<<HG, 256>>>(2, nullptr);  // ca -> cb  (+s1)
    k_sp<<<HG, 256>>>(3, out);      // cb -> sigmoid((c+s0)/3) -> out
}